// round 1
// baseline (speedup 1.0000x reference)
#include <cuda_runtime.h>
#include <math.h>

// NT-Xent loss, B=2048, D=512, N=4096, T=0.5.
// loss = (1/N) * sum_i [ 2 + log( sum_{j != i} exp(sim_ij - 2) ) - sim_{i,partner(i)} ]
// sim = (zn zn^T)/T, zn = row-normalized concat(z_i, z_j). sim in [-2,2] => fixed shift 2.

#define Bz 2048
#define Nn 4096
#define Dd 512

#define BM 64
#define BN 64
#define BK 32

// device scratch (no allocations allowed in kernel_launch)
__device__ float g_zn[Nn * Dd];      // 8 MB normalized embeddings
__device__ float g_rowsum[Nn];       // per-row sum of exp(sim - 2), excluding diagonal

// ---------------------------------------------------------------------------
// Kernel 1: row-normalize. One block per row, 128 threads, float4 per thread.
// Also zeroes g_rowsum and the output scalar.
// ---------------------------------------------------------------------------
__global__ void k_normalize(const float* __restrict__ zi,
                            const float* __restrict__ zj,
                            float* __restrict__ out) {
    int row = blockIdx.x;
    int t = threadIdx.x;  // 128 threads, 512 floats = 128 float4
    const float* src = (row < Bz) ? (zi + (size_t)row * Dd)
                                  : (zj + (size_t)(row - Bz) * Dd);
    float4 v = reinterpret_cast<const float4*>(src)[t];
    float ss = v.x * v.x + v.y * v.y + v.z * v.z + v.w * v.w;
#pragma unroll
    for (int o = 16; o > 0; o >>= 1) ss += __shfl_xor_sync(0xffffffffu, ss, o);
    __shared__ float red[4];
    if ((t & 31) == 0) red[t >> 5] = ss;
    __syncthreads();
    float tot = red[0] + red[1] + red[2] + red[3];
    float inv = 1.0f / fmaxf(sqrtf(tot), 1e-8f);
    float4 o4;
    o4.x = v.x * inv; o4.y = v.y * inv; o4.z = v.z * inv; o4.w = v.w * inv;
    reinterpret_cast<float4*>(g_zn + (size_t)row * Dd)[t] = o4;
    if (t == 0) g_rowsum[row] = 0.0f;
    if (t == 0 && row == 0) out[0] = 0.0f;
}

// ---------------------------------------------------------------------------
// Kernel 2: tiled syrk-like GEMM fused with exp + row reduction.
// Each block computes a 64x64 tile of sim = (zn zn^T)*2, applies
// exp(sim - 2) (diagonal masked), reduces per-row in smem, then one
// global atomicAdd per row.
// Block: 256 threads, 4x4 microtile per thread.
// ---------------------------------------------------------------------------
__global__ __launch_bounds__(256) void k_simexp() {
    __shared__ float As[BM][BK + 1];  // pitch 33 -> conflict-free transposed-ish access
    __shared__ float Bs[BN][BK + 1];
    __shared__ float rs[BM];

    int tid = threadIdx.x;
    int r0 = blockIdx.y * BM;
    int c0 = blockIdx.x * BN;

    int lr = tid >> 3;              // 0..31 (two row halves)
    int lk = (tid & 7) << 2;        // 0,4,...,28

    if (tid < BM) rs[tid] = 0.0f;

    float acc[4][4];
#pragma unroll
    for (int i = 0; i < 4; ++i)
#pragma unroll
        for (int j = 0; j < 4; ++j) acc[i][j] = 0.0f;

    int ty = tid >> 4;   // 0..15
    int tx = tid & 15;   // 0..15

    for (int k0 = 0; k0 < Dd; k0 += BK) {
#pragma unroll
        for (int h = 0; h < 2; ++h) {
            int r = lr + h * 32;
            float4 a = *reinterpret_cast<const float4*>(
                g_zn + (size_t)(r0 + r) * Dd + k0 + lk);
            As[r][lk + 0] = a.x; As[r][lk + 1] = a.y;
            As[r][lk + 2] = a.z; As[r][lk + 3] = a.w;
            float4 b = *reinterpret_cast<const float4*>(
                g_zn + (size_t)(c0 + r) * Dd + k0 + lk);
            Bs[r][lk + 0] = b.x; Bs[r][lk + 1] = b.y;
            Bs[r][lk + 2] = b.z; Bs[r][lk + 3] = b.w;
        }
        __syncthreads();

#pragma unroll
        for (int k = 0; k < BK; ++k) {
            float av[4], bv[4];
#pragma unroll
            for (int i = 0; i < 4; ++i) av[i] = As[ty * 4 + i][k];
#pragma unroll
            for (int j = 0; j < 4; ++j) bv[j] = Bs[tx * 4 + j][k];
#pragma unroll
            for (int i = 0; i < 4; ++i)
#pragma unroll
                for (int j = 0; j < 4; ++j)
                    acc[i][j] = fmaf(av[i], bv[j], acc[i][j]);
        }
        __syncthreads();
    }

    // sim = acc * 2 ; contribute exp(sim - 2) to each row's sum (mask diagonal)
#pragma unroll
    for (int i = 0; i < 4; ++i) {
        int gr = r0 + ty * 4 + i;
        float s = 0.0f;
#pragma unroll
        for (int j = 0; j < 4; ++j) {
            int gc = c0 + tx * 4 + j;
            float e = __expf(acc[i][j] * 2.0f - 2.0f);   // arg in [-4, 0]
            if (gr != gc) s += e;
        }
        atomicAdd(&rs[ty * 4 + i], s);
    }
    __syncthreads();
    if (tid < BM) atomicAdd(&g_rowsum[r0 + tid], rs[tid]);
}

// ---------------------------------------------------------------------------
// Kernel 3: finalize. One block per row: pos_i = 2*dot(zn_i, zn_partner),
// term_i = 2 + log(rowsum_i) - pos_i; accumulate mean into out.
// ---------------------------------------------------------------------------
__global__ void k_finalize(float* __restrict__ out) {
    int row = blockIdx.x;
    int t = threadIdx.x;  // 128
    int partner = (row < Bz) ? (row + Bz) : (row - Bz);
    float4 a = reinterpret_cast<const float4*>(g_zn + (size_t)row * Dd)[t];
    float4 b = reinterpret_cast<const float4*>(g_zn + (size_t)partner * Dd)[t];
    float d = a.x * b.x + a.y * b.y + a.z * b.z + a.w * b.w;
#pragma unroll
    for (int o = 16; o > 0; o >>= 1) d += __shfl_xor_sync(0xffffffffu, d, o);
    __shared__ float red[4];
    if ((t & 31) == 0) red[t >> 5] = d;
    __syncthreads();
    if (t == 0) {
        float dot = red[0] + red[1] + red[2] + red[3];
        float pos = dot * 2.0f;                       // /T
        float lse = 2.0f + logf(g_rowsum[row]);       // fixed-shift logsumexp
        atomicAdd(out, (lse - pos) * (1.0f / (float)Nn));
    }
}

extern "C" void kernel_launch(void* const* d_in, const int* in_sizes, int n_in,
                              void* d_out, int out_size) {
    const float* zi = (const float*)d_in[0];
    const float* zj = (const float*)d_in[1];
    float* out = (float*)d_out;

    k_normalize<<<Nn, 128>>>(zi, zj, out);
    dim3 grid(Nn / BN, Nn / BM);
    k_simexp<<<grid, 256>>>();
    k_finalize<<<Nn, 128>>>(out);
}

// round 4
// speedup vs baseline: 5.8065x; 5.8065x over previous
#include <cuda_runtime.h>
#include <cuda_bf16.h>
#include <cstdint>
#include <math.h>

// NT-Xent loss, B=2048, D=512, N=4096, T=0.5.
// loss = (1/N) * sum_i [ 2 + log( sum_{j != i} exp(sim_ij - 2) ) - sim_{i,partner(i)} ]
// sim = (zn zn^T)/T, zn = row-normalized concat(z_i, z_j). sim in [-2,2] =>
// fixed shift 2 (no row-max pass). GEMM in bf16 via mma.sync.m16n8k16 (HMMA,
// valid on both sm_103 and sm_103a), fused exp + row-sum epilogue.

#define Bz 2048
#define Nn 4096
#define Dd 512

__device__ float g_zn[Nn * Dd];            // fp32 normalized (exact pos term)
__device__ __nv_bfloat16 g_znh[Nn * Dd];   // bf16 normalized (GEMM operands)
__device__ float g_rowsum[Nn];             // sum_{j!=i} exp(sim_ij - 2)

// ---------------------------------------------------------------------------
// exp(2a-2) on the FMA pipe (no MUFU). 2^y with y = (a-1)*2*log2(e) in
// [-5.9, 0.1]; magic-add range reduction + deg-5 poly (rel err ~3e-6).
// ---------------------------------------------------------------------------
__device__ __forceinline__ float exp_sim(float a) {
    float y = fmaf(a, 2.8853900817779268f, -2.8853900817779268f);
    float z = y + 12582912.0f;                 // 1.5*2^23: round-to-nearest
    float f = y - (z - 12582912.0f);           // frac in [-0.5, 0.5]
    int ei = (__float_as_int(z) + (127 - 0x400000)) << 23;   // 2^round(y)
    float p = fmaf(f, 1.3333558146428443e-3f, 9.6181291076284771e-3f);
    p = fmaf(f, p, 5.5504108664821580e-2f);
    p = fmaf(f, p, 2.4022650695910071e-1f);
    p = fmaf(f, p, 6.9314718055994531e-1f);
    p = fmaf(f, p, 1.0f);
    return p * __int_as_float(ei);
}

// ---------------------------------------------------------------------------
// Kernel 1: row-normalize -> fp32 + bf16; zero rowsum + out.
// ---------------------------------------------------------------------------
__global__ void k_normalize(const float* __restrict__ zi,
                            const float* __restrict__ zj,
                            float* __restrict__ out) {
    int row = blockIdx.x;
    int t = threadIdx.x;  // 128 threads x float4 = 512 floats
    const float* src = (row < Bz) ? (zi + (size_t)row * Dd)
                                  : (zj + (size_t)(row - Bz) * Dd);
    float4 v = reinterpret_cast<const float4*>(src)[t];
    float ss = v.x * v.x + v.y * v.y + v.z * v.z + v.w * v.w;
#pragma unroll
    for (int o = 16; o > 0; o >>= 1) ss += __shfl_xor_sync(0xffffffffu, ss, o);
    __shared__ float red[4];
    if ((t & 31) == 0) red[t >> 5] = ss;
    __syncthreads();
    float tot = red[0] + red[1] + red[2] + red[3];
    float inv = 1.0f / fmaxf(sqrtf(tot), 1e-8f);
    float4 o4; o4.x = v.x * inv; o4.y = v.y * inv; o4.z = v.z * inv; o4.w = v.w * inv;
    reinterpret_cast<float4*>(g_zn + (size_t)row * Dd)[t] = o4;
    __nv_bfloat162* dh = reinterpret_cast<__nv_bfloat162*>(g_znh + (size_t)row * Dd);
    dh[2 * t + 0] = __floats2bfloat162_rn(o4.x, o4.y);
    dh[2 * t + 1] = __floats2bfloat162_rn(o4.z, o4.w);
    if (t == 0) g_rowsum[row] = 0.0f;
    if (t == 0 && row == 0) out[0] = 0.0f;
}

// ---------------------------------------------------------------------------
// Kernel 2: mma.sync bf16 fused sim-exp-rowsum.
// 128x128 tile per CTA (1024 CTAs). 8 warps (2x4), warp tile 64x32.
// K pipeline: 16 stages of 32 bf16 (64B), cp.async double buffer.
// SMEM rows padded to 80B (16B-aligned, ldmatrix bank-spread).
// ---------------------------------------------------------------------------
#define PITCH 80
#define TILE_BYTES (128 * PITCH)   // 10240 per operand per stage

__global__ __launch_bounds__(256) void k_simexp() {
    __shared__ __align__(128) char sA[2][TILE_BYTES];
    __shared__ __align__(128) char sB[2][TILE_BYTES];
    __shared__ float rs[128];

    int tid = threadIdx.x;
    int l = tid & 31;
    int wid = tid >> 5;
    int wm = wid >> 2;   // 0..1 : 64-row half
    int wn = wid & 3;    // 0..3 : 32-col quarter
    int r0 = (blockIdx.x & 31) * 128;
    int c0 = (blockIdx.x >> 5) * 128;
    const char* zb = (const char*)g_znh;   // row stride 1024B

    if (tid < 128) rs[tid] = 0.0f;

    uint32_t sA0 = (uint32_t)__cvta_generic_to_shared(&sA[0][0]);
    uint32_t sB0 = (uint32_t)__cvta_generic_to_shared(&sB[0][0]);

    // per-thread SMEM byte offsets within a stage (row-pitch 80)
    // A ldmatrix x4: threads 0-7 rows 0-7 b0 | 8-15 rows 8-15 b0 |
    //                16-23 rows 0-7 b16 | 24-31 rows 8-15 b16
    uint32_t aoff = (uint32_t)((64 * wm + (l & 15)) * PITCH + ((l >> 4) & 1) * 16);
    // B ldmatrix x4: n rows 0-7/8-15, k bytes 0/16
    uint32_t boff = (uint32_t)((32 * wn + (l & 7) + ((l >> 4) & 1) * 8) * PITCH
                               + ((l >> 3) & 1) * 16);

    float acc[4][4][4];
#pragma unroll
    for (int a = 0; a < 4; ++a)
#pragma unroll
        for (int b = 0; b < 4; ++b)
#pragma unroll
            for (int d = 0; d < 4; ++d) acc[a][b][d] = 0.0f;

    // cp.async: 1024 x 16B chunks per stage (A 512 + B 512), 4 per thread
    int cc = tid;                 // reuse pattern: chunk ids tid, tid+256, ...
    auto load_stage = [&](int s) {
        uint32_t koff = (uint32_t)s * 64u;   // 32 bf16 per stage
#pragma unroll
        for (int m = 0; m < 4; ++m) {
            int ch = cc + m * 256;           // 0..1023
            int half = ch >> 9;              // 0=A, 1=B
            int e = ch & 511;
            int row = e >> 2, seg = e & 3;
            uint32_t dst = (half ? sB0 : sA0)
                         + (uint32_t)(s & 1) * (uint32_t)TILE_BYTES
                         + (uint32_t)row * PITCH + (uint32_t)seg * 16u;
            const char* src = zb + (size_t)((half ? c0 : r0) + row) * 1024u
                            + koff + (uint32_t)seg * 16u;
            asm volatile("cp.async.cg.shared.global [%0], [%1], 16;"
                         :: "r"(dst), "l"(src) : "memory");
        }
        asm volatile("cp.async.commit_group;" ::: "memory");
    };

    load_stage(0);
    for (int s = 0; s < 16; ++s) {
        if (s + 1 < 16) {
            load_stage(s + 1);
            asm volatile("cp.async.wait_group 1;" ::: "memory");
        } else {
            asm volatile("cp.async.wait_group 0;" ::: "memory");
        }
        __syncthreads();

        uint32_t Ab = sA0 + (uint32_t)(s & 1) * (uint32_t)TILE_BYTES;
        uint32_t Bb = sB0 + (uint32_t)(s & 1) * (uint32_t)TILE_BYTES;
#pragma unroll
        for (int ks = 0; ks < 2; ++ks) {
            uint32_t kb = (uint32_t)ks * 32u;
            uint32_t a[4][4], bb[2][4];
#pragma unroll
            for (int mt = 0; mt < 4; ++mt)
                asm volatile(
                    "ldmatrix.sync.aligned.m8n8.x4.shared.b16 {%0,%1,%2,%3}, [%4];"
                    : "=r"(a[mt][0]), "=r"(a[mt][1]), "=r"(a[mt][2]), "=r"(a[mt][3])
                    : "r"(Ab + aoff + (uint32_t)mt * (16u * PITCH) + kb));
#pragma unroll
            for (int ng = 0; ng < 2; ++ng)
                asm volatile(
                    "ldmatrix.sync.aligned.m8n8.x4.shared.b16 {%0,%1,%2,%3}, [%4];"
                    : "=r"(bb[ng][0]), "=r"(bb[ng][1]), "=r"(bb[ng][2]), "=r"(bb[ng][3])
                    : "r"(Bb + boff + (uint32_t)ng * (16u * PITCH) + kb));
#pragma unroll
            for (int mt = 0; mt < 4; ++mt)
#pragma unroll
                for (int nt = 0; nt < 4; ++nt) {
                    uint32_t b0 = bb[nt >> 1][(nt & 1) * 2];
                    uint32_t b1 = bb[nt >> 1][(nt & 1) * 2 + 1];
                    asm volatile(
                        "mma.sync.aligned.m16n8k16.row.col.f32.bf16.bf16.f32 "
                        "{%0,%1,%2,%3}, {%4,%5,%6,%7}, {%8,%9}, {%0,%1,%2,%3};"
                        : "+f"(acc[mt][nt][0]), "+f"(acc[mt][nt][1]),
                          "+f"(acc[mt][nt][2]), "+f"(acc[mt][nt][3])
                        : "r"(a[mt][0]), "r"(a[mt][1]), "r"(a[mt][2]), "r"(a[mt][3]),
                          "r"(b0), "r"(b1));
                }
        }
        __syncthreads();
    }

    // Epilogue: D row = 64wm + 16mt + (l>>2) + 8*half ; col = 32wn + 8nt + (l&3)*2
#pragma unroll
    for (int mt = 0; mt < 4; ++mt) {
#pragma unroll
        for (int half = 0; half < 2; ++half) {
            int rl = 64 * wm + 16 * mt + (l >> 2) + 8 * half;
            int gr = r0 + rl;
            float v = 0.0f;
#pragma unroll
            for (int nt = 0; nt < 4; ++nt) {
                int gc = c0 + 32 * wn + 8 * nt + (l & 3) * 2;
                float e0 = exp_sim(acc[mt][nt][half * 2 + 0]);
                float e1 = exp_sim(acc[mt][nt][half * 2 + 1]);
                v += (gr == gc) ? 0.0f : e0;
                v += (gr == gc + 1) ? 0.0f : e1;
            }
            v += __shfl_xor_sync(0xffffffffu, v, 1);
            v += __shfl_xor_sync(0xffffffffu, v, 2);
            if ((l & 3) == 0) atomicAdd(&rs[rl], v);
        }
    }
    __syncthreads();
    if (tid < 128) atomicAdd(&g_rowsum[r0 + tid], rs[tid]);
}

// ---------------------------------------------------------------------------
// Kernel 3: finalize (exact fp32 pos term), accumulate mean into out.
// ---------------------------------------------------------------------------
__global__ void k_finalize(float* __restrict__ out) {
    int row = blockIdx.x;
    int t = threadIdx.x;  // 128
    int partner = (row < Bz) ? (row + Bz) : (row - Bz);
    float4 a = reinterpret_cast<const float4*>(g_zn + (size_t)row * Dd)[t];
    float4 b = reinterpret_cast<const float4*>(g_zn + (size_t)partner * Dd)[t];
    float d = a.x * b.x + a.y * b.y + a.z * b.z + a.w * b.w;
#pragma unroll
    for (int o = 16; o > 0; o >>= 1) d += __shfl_xor_sync(0xffffffffu, d, o);
    __shared__ float red[4];
    if ((t & 31) == 0) red[t >> 5] = d;
    __syncthreads();
    if (t == 0) {
        float pos = (red[0] + red[1] + red[2] + red[3]) * 2.0f;  // /T
        float lse = 2.0f + logf(g_rowsum[row]);
        atomicAdd(out, (lse - pos) * (1.0f / (float)Nn));
    }
}

extern "C" void kernel_launch(void* const* d_in, const int* in_sizes, int n_in,
                              void* d_out, int out_size) {
    const float* zi = (const float*)d_in[0];
    const float* zj = (const float*)d_in[1];
    float* out = (float*)d_out;

    k_normalize<<<Nn, 128>>>(zi, zj, out);
    k_simexp<<<1024, 256>>>();
    k_finalize<<<Nn, 128>>>(out);
}

// round 5
// speedup vs baseline: 9.5629x; 1.6469x over previous
#include <cuda_runtime.h>
#include <cuda_bf16.h>
#include <cstdint>
#include <math.h>

// NT-Xent loss, B=2048, D=512, N=4096, T=0.5.
// loss = (1/N) * sum_i [ 2 + log( sum_{j != i} exp(sim_ij - 2) ) - sim_{i,partner(i)} ]
// sim = (zn zn^T)/T in [-2,2] => fixed shift 2, single pass, no row max.
// bf16 mma.sync GEMM over UPPER-TRIANGULAR tiles only (sim symmetric):
// each off-diagonal tile contributes to rowsum[rows] AND rowsum[cols].

#define Bz 2048
#define Nn 4096
#define Dd 512

__device__ __nv_bfloat16 g_znh[Nn * Dd];   // bf16 normalized (4 MB, L2-resident)
__device__ float g_rowsum[Nn];             // sum_{j!=i} exp(sim_ij - 2)
__device__ float g_pos[Nn];                // dot(zn_i, zn_partner)

// ---------------------------------------------------------------------------
// exp(2a-2) on the FMA pipe (no MUFU). 2^y, y=(a-1)*2log2e in [-5.9, 0.1];
// magic-add range reduction + deg-5 poly (rel err ~3e-6).
// ---------------------------------------------------------------------------
__device__ __forceinline__ float exp_sim(float a) {
    float y = fmaf(a, 2.8853900817779268f, -2.8853900817779268f);
    float z = y + 12582912.0f;
    float f = y - (z - 12582912.0f);
    int ei = (__float_as_int(z) + (127 - 0x400000)) << 23;
    float p = fmaf(f, 1.3333558146428443e-3f, 9.6181291076284771e-3f);
    p = fmaf(f, p, 5.5504108664821580e-2f);
    p = fmaf(f, p, 2.4022650695910071e-1f);
    p = fmaf(f, p, 6.9314718055994531e-1f);
    p = fmaf(f, p, 1.0f);
    return p * __int_as_float(ei);
}

// ---------------------------------------------------------------------------
// Kernel 1: row-normalize -> bf16 only; zero rowsum + out.
// ---------------------------------------------------------------------------
__global__ void k_normalize(const float* __restrict__ zi,
                            const float* __restrict__ zj,
                            float* __restrict__ out) {
    int row = blockIdx.x;
    int t = threadIdx.x;  // 128 threads x float4
    const float* src = (row < Bz) ? (zi + (size_t)row * Dd)
                                  : (zj + (size_t)(row - Bz) * Dd);
    float4 v = reinterpret_cast<const float4*>(src)[t];
    float ss = v.x * v.x + v.y * v.y + v.z * v.z + v.w * v.w;
#pragma unroll
    for (int o = 16; o > 0; o >>= 1) ss += __shfl_xor_sync(0xffffffffu, ss, o);
    __shared__ float red[4];
    if ((t & 31) == 0) red[t >> 5] = ss;
    __syncthreads();
    float tot = red[0] + red[1] + red[2] + red[3];
    float inv = 1.0f / fmaxf(sqrtf(tot), 1e-8f);
    __nv_bfloat162* dh = reinterpret_cast<__nv_bfloat162*>(g_znh + (size_t)row * Dd);
    dh[2 * t + 0] = __floats2bfloat162_rn(v.x * inv, v.y * inv);
    dh[2 * t + 1] = __floats2bfloat162_rn(v.z * inv, v.w * inv);
    if (t == 0) g_rowsum[row] = 0.0f;
    if (t == 0 && row == 0) out[0] = 0.0f;
}

// ---------------------------------------------------------------------------
// Kernel 2: upper-triangular fused sim-exp-rowsum.
// 528 CTAs; CTA k -> tile (ti, tj), tj >= ti, 128x128 per tile.
// 8 warps (2x4), warp tile 64x32, 16-stage K pipeline, cp.async double buffer.
// ---------------------------------------------------------------------------
#define PITCH 80
#define TILE_BYTES (128 * PITCH)

__global__ __launch_bounds__(256) void k_simexp() {
    __shared__ __align__(128) char sA[2][TILE_BYTES];
    __shared__ __align__(128) char sB[2][TILE_BYTES];
    __shared__ float rs_row[128];
    __shared__ float rs_col[128];

    int tid = threadIdx.x;
    int l = tid & 31;
    int wid = tid >> 5;
    int wm = wid >> 2;   // 0..1
    int wn = wid & 3;    // 0..3

    // decode triangular index: k -> (ti, tj), start(ti) = 32*ti - ti*(ti-1)/2
    int k = blockIdx.x;
    int ti = (int)((65.0f - sqrtf(4225.0f - 8.0f * (float)k)) * 0.5f);
    while ((ti + 1) * 32 - ((ti + 1) * ti) / 2 <= k) ++ti;
    while (ti * 32 - (ti * (ti - 1)) / 2 > k) --ti;
    int tj = ti + (k - (ti * 32 - (ti * (ti - 1)) / 2));
    int r0 = ti * 128, c0 = tj * 128;
    bool dual = (ti != tj);
    bool postile = (tj - ti) == 16;
    const char* zb = (const char*)g_znh;   // row stride 1024B

    if (tid < 128) { rs_row[tid] = 0.0f; rs_col[tid] = 0.0f; }

    uint32_t sA0 = (uint32_t)__cvta_generic_to_shared(&sA[0][0]);
    uint32_t sB0 = (uint32_t)__cvta_generic_to_shared(&sB[0][0]);

    uint32_t aoff = (uint32_t)((64 * wm + (l & 15)) * PITCH + ((l >> 4) & 1) * 16);
    uint32_t boff = (uint32_t)((32 * wn + (l & 7) + ((l >> 4) & 1) * 8) * PITCH
                               + ((l >> 3) & 1) * 16);

    float acc[4][4][4];
#pragma unroll
    for (int a = 0; a < 4; ++a)
#pragma unroll
        for (int b = 0; b < 4; ++b)
#pragma unroll
            for (int d = 0; d < 4; ++d) acc[a][b][d] = 0.0f;

    auto load_stage = [&](int s) {
        uint32_t koff = (uint32_t)s * 64u;   // 32 bf16 per stage
#pragma unroll
        for (int m = 0; m < 4; ++m) {
            int ch = tid + m * 256;          // 0..1023 16B chunks
            int half = ch >> 9;              // 0=A, 1=B
            int e = ch & 511;
            int row = e >> 2, seg = e & 3;
            uint32_t dst = (half ? sB0 : sA0)
                         + (uint32_t)(s & 1) * (uint32_t)TILE_BYTES
                         + (uint32_t)row * PITCH + (uint32_t)seg * 16u;
            const char* src = zb + (size_t)((half ? c0 : r0) + row) * 1024u
                            + koff + (uint32_t)seg * 16u;
            asm volatile("cp.async.cg.shared.global [%0], [%1], 16;"
                         :: "r"(dst), "l"(src) : "memory");
        }
        asm volatile("cp.async.commit_group;" ::: "memory");
    };

    load_stage(0);
    for (int s = 0; s < 16; ++s) {
        if (s + 1 < 16) {
            load_stage(s + 1);
            asm volatile("cp.async.wait_group 1;" ::: "memory");
        } else {
            asm volatile("cp.async.wait_group 0;" ::: "memory");
        }
        __syncthreads();

        uint32_t Ab = sA0 + (uint32_t)(s & 1) * (uint32_t)TILE_BYTES;
        uint32_t Bb = sB0 + (uint32_t)(s & 1) * (uint32_t)TILE_BYTES;
#pragma unroll
        for (int ks = 0; ks < 2; ++ks) {
            uint32_t kb = (uint32_t)ks * 32u;
            uint32_t a[4][4], bb[2][4];
#pragma unroll
            for (int mt = 0; mt < 4; ++mt)
                asm volatile(
                    "ldmatrix.sync.aligned.m8n8.x4.shared.b16 {%0,%1,%2,%3}, [%4];"
                    : "=r"(a[mt][0]), "=r"(a[mt][1]), "=r"(a[mt][2]), "=r"(a[mt][3])
                    : "r"(Ab + aoff + (uint32_t)mt * (16u * PITCH) + kb));
#pragma unroll
            for (int ng = 0; ng < 2; ++ng)
                asm volatile(
                    "ldmatrix.sync.aligned.m8n8.x4.shared.b16 {%0,%1,%2,%3}, [%4];"
                    : "=r"(bb[ng][0]), "=r"(bb[ng][1]), "=r"(bb[ng][2]), "=r"(bb[ng][3])
                    : "r"(Bb + boff + (uint32_t)ng * (16u * PITCH) + kb));
#pragma unroll
            for (int mt = 0; mt < 4; ++mt)
#pragma unroll
                for (int nt = 0; nt < 4; ++nt) {
                    uint32_t b0 = bb[nt >> 1][(nt & 1) * 2];
                    uint32_t b1 = bb[nt >> 1][(nt & 1) * 2 + 1];
                    asm volatile(
                        "mma.sync.aligned.m16n8k16.row.col.f32.bf16.bf16.f32 "
                        "{%0,%1,%2,%3}, {%4,%5,%6,%7}, {%8,%9}, {%0,%1,%2,%3};"
                        : "+f"(acc[mt][nt][0]), "+f"(acc[mt][nt][1]),
                          "+f"(acc[mt][nt][2]), "+f"(acc[mt][nt][3])
                        : "r"(a[mt][0]), "r"(a[mt][1]), "r"(a[mt][2]), "r"(a[mt][3]),
                          "r"(b0), "r"(b1));
                }
        }
        __syncthreads();
    }

    // Epilogue. D row = 64wm + 16mt + (l>>2) + 8*half ; col = 32wn + 8nt + (l&3)*2.
    // Row sums (diag masked) + column sums (for the mirrored lower triangle).
    float vcol[4][2];
#pragma unroll
    for (int nt = 0; nt < 4; ++nt) { vcol[nt][0] = 0.0f; vcol[nt][1] = 0.0f; }

#pragma unroll
    for (int mt = 0; mt < 4; ++mt) {
#pragma unroll
        for (int half = 0; half < 2; ++half) {
            int rl = 64 * wm + 16 * mt + (l >> 2) + 8 * half;
            int gr = r0 + rl;
            float v = 0.0f;
#pragma unroll
            for (int nt = 0; nt < 4; ++nt) {
                int gc = c0 + 32 * wn + 8 * nt + (l & 3) * 2;
                float d0 = acc[mt][nt][half * 2 + 0];
                float d1 = acc[mt][nt][half * 2 + 1];
                float e0 = exp_sim(d0);
                float e1 = exp_sim(d1);
                if (postile) {   // positive-pair diagonal lives in these tiles
                    if (gc == gr + Bz)     { g_pos[gr] = d0; g_pos[gc] = d0; }
                    if (gc + 1 == gr + Bz) { g_pos[gr] = d1; g_pos[gc + 1] = d1; }
                }
                v += (gr == gc) ? 0.0f : e0;
                v += (gr == gc + 1) ? 0.0f : e1;
                vcol[nt][0] += e0;
                vcol[nt][1] += e1;
            }
            v += __shfl_xor_sync(0xffffffffu, v, 1);
            v += __shfl_xor_sync(0xffffffffu, v, 2);
            if ((l & 3) == 0) atomicAdd(&rs_row[rl], v);
        }
    }
    if (dual) {
#pragma unroll
        for (int nt = 0; nt < 4; ++nt) {
            float cv0 = vcol[nt][0], cv1 = vcol[nt][1];
#pragma unroll
            for (int o = 4; o <= 16; o <<= 1) {
                cv0 += __shfl_xor_sync(0xffffffffu, cv0, o);
                cv1 += __shfl_xor_sync(0xffffffffu, cv1, o);
            }
            if ((l >> 2) == 0) {
                int cl = 32 * wn + 8 * nt + (l & 3) * 2;
                atomicAdd(&rs_col[cl], cv0);
                atomicAdd(&rs_col[cl + 1], cv1);
            }
        }
    }
    __syncthreads();
    if (tid < 128) {
        atomicAdd(&g_rowsum[r0 + tid], rs_row[tid]);
        if (dual) atomicAdd(&g_rowsum[c0 + tid], rs_col[tid]);
    }
}

// ---------------------------------------------------------------------------
// Kernel 3: finalize. loss_i = 2 + log(rowsum_i) - 2*pos_i ; mean into out.
// ---------------------------------------------------------------------------
__global__ void k_finalize(float* __restrict__ out) {
    int i = blockIdx.x * 256 + threadIdx.x;
    float term = 2.0f + logf(g_rowsum[i]) - 2.0f * g_pos[i];
    int l = threadIdx.x & 31;
#pragma unroll
    for (int o = 16; o > 0; o >>= 1) term += __shfl_xor_sync(0xffffffffu, term, o);
    __shared__ float red[8];
    if (l == 0) red[threadIdx.x >> 5] = term;
    __syncthreads();
    if (threadIdx.x == 0) {
        float s = 0.0f;
#pragma unroll
        for (int w = 0; w < 8; ++w) s += red[w];
        atomicAdd(out, s * (1.0f / (float)Nn));
    }
}

extern "C" void kernel_launch(void* const* d_in, const int* in_sizes, int n_in,
                              void* d_out, int out_size) {
    const float* zi = (const float*)d_in[0];
    const float* zj = (const float*)d_in[1];
    float* out = (float*)d_out;

    k_normalize<<<Nn, 128>>>(zi, zj, out);
    k_simexp<<<528, 256>>>();
    k_finalize<<<Nn / 256, 256>>>(out);
}